// round 2
// baseline (speedup 1.0000x reference)
#include <cuda_runtime.h>
#include <cuda_bf16.h>

// Problem constants (fixed by the dataset)
#define BB    4
#define SS    4096
#define DD    1024
#define MM    (BB * SS)      // 16384 rows
#define NN    (2 * DD)       // 2048  cols of hg
#define KK    DD             // 1024  reduction

#define NCHUNK 32
#define CLEN   (SS / NCHUNK) // 128

// Scratch: GEMM output hg [M, 2N] + chunk-scan carries. Static device globals
// (allowed; no runtime allocation).
__device__ float g_hg[(size_t)MM * NN];          // 128 MiB
__device__ float g_chunkC[NCHUNK * BB * DD];     // [k][ch]
__device__ float g_chunkV[NCHUNK * BB * DD];
__device__ float g_h0[NCHUNK * BB * DD];

// ---------------------------------------------------------------------------
// GEMM: hg[m,n] = sum_k x[m,k] * W[n,k]   (both K-contiguous, "NT" layout)
// BM=BN=128, BK=8, 256 threads, 8x8 microtile per thread.
// ---------------------------------------------------------------------------
#define BM 128
#define BN 128
#define BKt 8

__global__ __launch_bounds__(256, 2)
void gemm_kernel(const float* __restrict__ A, const float* __restrict__ B)
{
    __shared__ float As[BKt][BM];
    __shared__ float Bs[BKt][BN];

    const int tid = threadIdx.x;
    const int m0  = blockIdx.y * BM;
    const int n0  = blockIdx.x * BN;

    // Global load mapping: each thread loads one float4 of A and one of B per k-tile.
    const int lrow = tid >> 1;            // 0..127
    const int lk   = (tid & 1) * 4;       // 0 or 4
    const float* Aptr = A + (size_t)(m0 + lrow) * KK + lk;
    const float* Bptr = B + (size_t)(n0 + lrow) * KK + lk;

    const int ty = tid >> 4;              // 0..15 -> row group
    const int tx = tid & 15;              // 0..15 -> col group

    float acc[8][8];
#pragma unroll
    for (int i = 0; i < 8; i++)
#pragma unroll
        for (int j = 0; j < 8; j++) acc[i][j] = 0.f;

    for (int kt = 0; kt < KK; kt += BKt) {
        const float4 av = *(const float4*)(Aptr + kt);
        const float4 bv = *(const float4*)(Bptr + kt);

        __syncthreads();   // previous tile's consumers done
        As[lk + 0][lrow] = av.x;
        As[lk + 1][lrow] = av.y;
        As[lk + 2][lrow] = av.z;
        As[lk + 3][lrow] = av.w;
        Bs[lk + 0][lrow] = bv.x;
        Bs[lk + 1][lrow] = bv.y;
        Bs[lk + 2][lrow] = bv.z;
        Bs[lk + 3][lrow] = bv.w;
        __syncthreads();

#pragma unroll
        for (int kk = 0; kk < BKt; kk++) {
            float a[8], b[8];
            const float4 a0 = *(const float4*)&As[kk][ty * 8];
            const float4 a1 = *(const float4*)&As[kk][ty * 8 + 4];
            const float4 b0 = *(const float4*)&Bs[kk][tx * 8];
            const float4 b1 = *(const float4*)&Bs[kk][tx * 8 + 4];
            a[0]=a0.x; a[1]=a0.y; a[2]=a0.z; a[3]=a0.w;
            a[4]=a1.x; a[5]=a1.y; a[6]=a1.z; a[7]=a1.w;
            b[0]=b0.x; b[1]=b0.y; b[2]=b0.z; b[3]=b0.w;
            b[4]=b1.x; b[5]=b1.y; b[6]=b1.z; b[7]=b1.w;
#pragma unroll
            for (int i = 0; i < 8; i++)
#pragma unroll
                for (int j = 0; j < 8; j++)
                    acc[i][j] = fmaf(a[i], b[j], acc[i][j]);
        }
    }

    // Store 8x8 tile, vectorized float4.
#pragma unroll
    for (int i = 0; i < 8; i++) {
        float* crow = g_hg + (size_t)(m0 + ty * 8 + i) * NN + n0 + tx * 8;
        float4 v0 = make_float4(acc[i][0], acc[i][1], acc[i][2], acc[i][3]);
        float4 v1 = make_float4(acc[i][4], acc[i][5], acc[i][6], acc[i][7]);
        *(float4*)(crow)     = v0;
        *(float4*)(crow + 4) = v1;
    }
}

// ---------------------------------------------------------------------------
// Elementwise: c = sigmoid(-gate), v = sigmoid(gate) * g(hidden)
// g(x) = x + 0.5 (x>=0) else sigmoid(x)
// ---------------------------------------------------------------------------
__device__ __forceinline__ void compute_cv(float hidden, float gate,
                                           float& c, float& v)
{
    const float eg = __expf(gate);
    c = 1.f / (1.f + eg);                  // sigmoid(-gate)
    const float z = 1.f - c;               // sigmoid(gate)
    float gg;
    if (hidden >= 0.f) {
        gg = hidden + 0.5f;
    } else {
        gg = 1.f / (1.f + __expf(-hidden)); // sigmoid(hidden)
    }
    v = z * gg;
}

// ---------------------------------------------------------------------------
// Pass A: per (channel, chunk) compute composed transform (C, V):
//   start (C=1, V=0); per step s: V = c_s*V + v_s; C = c_s*C.
// Grid: (D/128, NCHUNK, B), 128 threads. Fully coalesced (d fastest).
// ---------------------------------------------------------------------------
__global__ __launch_bounds__(128)
void scan_passA()
{
    const int d = blockIdx.x * 128 + threadIdx.x;
    const int k = blockIdx.y;
    const int b = blockIdx.z;

    const size_t base = ((size_t)b * SS + (size_t)k * CLEN) * NN;
    const float* ph = g_hg + base + d;         // hidden stream
    const float* pg = g_hg + base + DD + d;    // gate   stream

    float C = 1.f, V = 0.f;
#pragma unroll 4
    for (int s = 0; s < CLEN; s++) {
        const float hidden = ph[(size_t)s * NN];
        const float gate   = pg[(size_t)s * NN];
        float c, v;
        compute_cv(hidden, gate, c, v);
        V = fmaf(c, V, v);
        C = C * c;
    }
    const int ch = b * DD + d;
    g_chunkC[k * (BB * DD) + ch] = C;
    g_chunkV[k * (BB * DD) + ch] = V;
}

// ---------------------------------------------------------------------------
// Pass B: per channel, exclusive scan over NCHUNK chunk transforms to get the
// starting h for every chunk. 4096 threads total, coalesced [k][ch] layout.
// ---------------------------------------------------------------------------
__global__ __launch_bounds__(128)
void scan_passB()
{
    const int ch = blockIdx.x * 128 + threadIdx.x;  // 0..4095
    float h = 0.f;   // h0 = 0 (reference has no initial-state term)
#pragma unroll
    for (int k = 0; k < NCHUNK; k++) {
        g_h0[k * (BB * DD) + ch] = h;
        h = fmaf(g_chunkC[k * (BB * DD) + ch], h, g_chunkV[k * (BB * DD) + ch]);
    }
}

// ---------------------------------------------------------------------------
// Pass C: re-run the recurrence within each chunk starting from h0, write out.
// ---------------------------------------------------------------------------
__global__ __launch_bounds__(128)
void scan_passC(float* __restrict__ out)
{
    const int d = blockIdx.x * 128 + threadIdx.x;
    const int k = blockIdx.y;
    const int b = blockIdx.z;

    const size_t base = ((size_t)b * SS + (size_t)k * CLEN) * NN;
    const float* ph = g_hg + base + d;
    const float* pg = g_hg + base + DD + d;

    const int ch = b * DD + d;
    float h = g_h0[k * (BB * DD) + ch];

    float* po = out + ((size_t)b * SS + (size_t)k * CLEN) * DD + d;
#pragma unroll 4
    for (int s = 0; s < CLEN; s++) {
        const float hidden = ph[(size_t)s * NN];
        const float gate   = pg[(size_t)s * NN];
        float c, v;
        compute_cv(hidden, gate, c, v);
        h = fmaf(c, h, v);
        po[(size_t)s * DD] = h;
    }
}

// ---------------------------------------------------------------------------
extern "C" void kernel_launch(void* const* d_in, const int* in_sizes, int n_in,
                              void* d_out, int out_size)
{
    const float* x = (const float*)d_in[0];   // [B, S, D]
    const float* W = (const float*)d_in[1];   // [2D, D]
    float* out = (float*)d_out;               // [B, S, D] fp32

    dim3 ggrid(NN / BN, MM / BM);             // (16, 128)
    gemm_kernel<<<ggrid, 256>>>(x, W);

    dim3 sgrid(DD / 128, NCHUNK, BB);         // (8, 32, 4)
    scan_passA<<<sgrid, 128>>>();
    scan_passB<<<(BB * DD) / 128, 128>>>();
    scan_passC<<<sgrid, 128>>>(out);
}

// round 6
// speedup vs baseline: 1.7555x; 1.7555x over previous
#include <cuda_runtime.h>
#include <cuda_bf16.h>
#include <cstdint>

// Problem constants
#define BB    4
#define SS    4096
#define DD    1024
#define MM    (BB * SS)      // 16384
#define NN    (2 * DD)       // 2048
#define KK    DD             // 1024

#define NCHUNK 128
#define CLEN   (SS / NCHUNK) // 32

// Scratch (static device globals; no runtime allocation)
__device__ float g_hg[(size_t)MM * NN];          // 128 MiB
__device__ float g_chunkC[NCHUNK * BB * DD];
__device__ float g_chunkV[NCHUNK * BB * DD];
__device__ float g_h0[NCHUNK * BB * DD];

// ===========================================================================
// bf16 split helpers
// ===========================================================================
__device__ __forceinline__ uint32_t f2bf_bits(float x) {
    uint32_t u = __float_as_uint(x);
    return (u + 0x7FFFu + ((u >> 16) & 1u)) >> 16;
}
__device__ __forceinline__ float bf2f(uint32_t b) {
    return __uint_as_float(b << 16);
}
__device__ __forceinline__ void split4(float4 v, uint2& hi, uint2& lo) {
    uint32_t h0 = f2bf_bits(v.x), h1 = f2bf_bits(v.y);
    uint32_t h2 = f2bf_bits(v.z), h3 = f2bf_bits(v.w);
    float l0 = v.x - bf2f(h0), l1 = v.y - bf2f(h1);
    float l2 = v.z - bf2f(h2), l3 = v.w - bf2f(h3);
    uint32_t a0 = f2bf_bits(l0), a1 = f2bf_bits(l1);
    uint32_t a2 = f2bf_bits(l2), a3 = f2bf_bits(l3);
    hi = make_uint2(h0 | (h1 << 16), h2 | (h3 << 16));
    lo = make_uint2(a0 | (a1 << 16), a2 | (a3 << 16));
}

__device__ __forceinline__ void mma_bf16(float& d0, float& d1, float& d2, float& d3,
                                         uint32_t a0, uint32_t a1, uint32_t a2, uint32_t a3,
                                         uint32_t b0, uint32_t b1)
{
    asm volatile(
        "mma.sync.aligned.m16n8k16.row.col.f32.bf16.bf16.f32 "
        "{%0,%1,%2,%3}, {%4,%5,%6,%7}, {%8,%9}, {%0,%1,%2,%3};"
        : "+f"(d0), "+f"(d1), "+f"(d2), "+f"(d3)
        : "r"(a0), "r"(a1), "r"(a2), "r"(a3), "r"(b0), "r"(b1));
}

// ===========================================================================
// GEMM: hg[m,n] = sum_k x[m,k]*W[n,k] via bf16 split-2 (3 products), fp32 acc.
// CTA 128x128, BK=32 fp32, 256 threads (8 warps, warp tile 64x32).
// smem tiles padded: row stride 40 bf16 (80 B) -> conflict-free frag LDS.
// ===========================================================================
#define TM 128
#define TN 128
#define TKC 32
#define KCHUNKS (KK / TKC)            // 32
#define ROWB 80                        // bytes per smem row (40 bf16)
#define ARR_BYTES (128 * ROWB)         // 10240 per array
#define STAGE_BYTES (4 * ARR_BYTES)    // Ahi, Alo, Bhi, Blo
#define GEMM_SMEM (2 * STAGE_BYTES)    // 81920

__global__ __launch_bounds__(256, 1)
void mingru_gemm(const float* __restrict__ A, const float* __restrict__ B)
{
    extern __shared__ char smem[];
    const int tid = threadIdx.x;
    const int wid = tid >> 5, lid = tid & 31;
    const int m0 = blockIdx.y * TM, n0 = blockIdx.x * TN;

    // Global load mapping: 2 threads per 32-float row; 4 float4 each.
    const int grow = tid >> 1;                 // 0..127
    const int gseg = tid & 1;                  // 0..1 (k half: 0..15 / 16..31)
    const float* Ag = A + (size_t)(m0 + grow) * KK + gseg * 16;
    const float* Bg = B + (size_t)(n0 + grow) * KK + gseg * 16;
    const uint32_t stsoff = (uint32_t)(grow * ROWB + gseg * 32);  // + i*8

    // Warp tiling: 2 (m) x 4 (n) warps; warp tile 64x32.
    const int wm = (wid >> 2) * 64;
    const int wn = (wid & 3) * 32;
    const int g  = lid >> 2;                   // 0..7
    const int t  = lid & 3;                    // 0..3

    float acc[4][4][4];
#pragma unroll
    for (int i = 0; i < 4; i++)
#pragma unroll
        for (int j = 0; j < 4; j++)
#pragma unroll
            for (int e = 0; e < 4; e++) acc[i][j][e] = 0.f;

    float4 pa[4], pb[4];

    // Prologue: chunk 0 -> stage 0
#pragma unroll
    for (int i = 0; i < 4; i++) {
        pa[i] = *(const float4*)(Ag + i * 4);
        pb[i] = *(const float4*)(Bg + i * 4);
    }
    {
        char* Ah = smem;
        char* Al = smem + ARR_BYTES;
        char* Bh = smem + 2 * ARR_BYTES;
        char* Bl = smem + 3 * ARR_BYTES;
#pragma unroll
        for (int i = 0; i < 4; i++) {
            uint2 hi, lo;
            split4(pa[i], hi, lo);
            *(uint2*)(Ah + stsoff + i * 8) = hi;
            *(uint2*)(Al + stsoff + i * 8) = lo;
            split4(pb[i], hi, lo);
            *(uint2*)(Bh + stsoff + i * 8) = hi;
            *(uint2*)(Bl + stsoff + i * 8) = lo;
        }
    }
    __syncthreads();

    for (int kc = 0; kc < KCHUNKS; kc++) {
        // Prefetch next chunk (issued before compute to hide latency)
        if (kc + 1 < KCHUNKS) {
#pragma unroll
            for (int i = 0; i < 4; i++) {
                pa[i] = *(const float4*)(Ag + (kc + 1) * TKC + i * 4);
                pb[i] = *(const float4*)(Bg + (kc + 1) * TKC + i * 4);
            }
        }

        const char* st = smem + (kc & 1) * STAGE_BYTES;
        const char* Ah = st;
        const char* Al = st + ARR_BYTES;
        const char* Bh = st + 2 * ARR_BYTES;
        const char* Bl = st + 3 * ARR_BYTES;

#pragma unroll
        for (int kt = 0; kt < 2; kt++) {
            const int cbyte = kt * 32 + t * 4;   // (kt*16 + t*2) * 2 bytes
            uint32_t af[4][4], bf[4][2];

            // --- Bhi frags ---
#pragma unroll
            for (int j = 0; j < 4; j++) {
                const int r = wn + j * 8 + g;
                bf[j][0] = *(const uint32_t*)(Bh + r * ROWB + cbyte);
                bf[j][1] = *(const uint32_t*)(Bh + r * ROWB + cbyte + 16);
            }
            // --- Ahi frags ---
#pragma unroll
            for (int i = 0; i < 4; i++) {
                const int r = wm + i * 16 + g;
                af[i][0] = *(const uint32_t*)(Ah + r * ROWB + cbyte);
                af[i][1] = *(const uint32_t*)(Ah + (r + 8) * ROWB + cbyte);
                af[i][2] = *(const uint32_t*)(Ah + r * ROWB + cbyte + 16);
                af[i][3] = *(const uint32_t*)(Ah + (r + 8) * ROWB + cbyte + 16);
            }
            // hi * hi
#pragma unroll
            for (int i = 0; i < 4; i++)
#pragma unroll
                for (int j = 0; j < 4; j++)
                    mma_bf16(acc[i][j][0], acc[i][j][1], acc[i][j][2], acc[i][j][3],
                             af[i][0], af[i][1], af[i][2], af[i][3],
                             bf[j][0], bf[j][1]);
            // hi * Blo
            {
                uint32_t bl[4][2];
#pragma unroll
                for (int j = 0; j < 4; j++) {
                    const int r = wn + j * 8 + g;
                    bl[j][0] = *(const uint32_t*)(Bl + r * ROWB + cbyte);
                    bl[j][1] = *(const uint32_t*)(Bl + r * ROWB + cbyte + 16);
                }
#pragma unroll
                for (int i = 0; i < 4; i++)
#pragma unroll
                    for (int j = 0; j < 4; j++)
                        mma_bf16(acc[i][j][0], acc[i][j][1], acc[i][j][2], acc[i][j][3],
                                 af[i][0], af[i][1], af[i][2], af[i][3],
                                 bl[j][0], bl[j][1]);
            }
            // Alo * Bhi (reuse af regs)
#pragma unroll
            for (int i = 0; i < 4; i++) {
                const int r = wm + i * 16 + g;
                af[i][0] = *(const uint32_t*)(Al + r * ROWB + cbyte);
                af[i][1] = *(const uint32_t*)(Al + (r + 8) * ROWB + cbyte);
                af[i][2] = *(const uint32_t*)(Al + r * ROWB + cbyte + 16);
                af[i][3] = *(const uint32_t*)(Al + (r + 8) * ROWB + cbyte + 16);
            }
#pragma unroll
            for (int i = 0; i < 4; i++)
#pragma unroll
                for (int j = 0; j < 4; j++)
                    mma_bf16(acc[i][j][0], acc[i][j][1], acc[i][j][2], acc[i][j][3],
                             af[i][0], af[i][1], af[i][2], af[i][3],
                             bf[j][0], bf[j][1]);
        }
        __syncthreads();

        if (kc + 1 < KCHUNKS) {
            char* nst = smem + ((kc + 1) & 1) * STAGE_BYTES;
            char* nAh = nst;
            char* nAl = nst + ARR_BYTES;
            char* nBh = nst + 2 * ARR_BYTES;
            char* nBl = nst + 3 * ARR_BYTES;
#pragma unroll
            for (int i = 0; i < 4; i++) {
                uint2 hi, lo;
                split4(pa[i], hi, lo);
                *(uint2*)(nAh + stsoff + i * 8) = hi;
                *(uint2*)(nAl + stsoff + i * 8) = lo;
                split4(pb[i], hi, lo);
                *(uint2*)(nBh + stsoff + i * 8) = hi;
                *(uint2*)(nBl + stsoff + i * 8) = lo;
            }
            __syncthreads();
        }
    }

    // Epilogue: write accumulators (D mapping of m16n8: c0/c1 row g, c2/c3 row g+8)
#pragma unroll
    for (int i = 0; i < 4; i++) {
        const int r0 = m0 + wm + i * 16 + g;
#pragma unroll
        for (int j = 0; j < 4; j++) {
            const int c = n0 + wn + j * 8 + t * 2;
            *(float2*)(g_hg + (size_t)r0 * NN + c) =
                make_float2(acc[i][j][0], acc[i][j][1]);
            *(float2*)(g_hg + (size_t)(r0 + 8) * NN + c) =
                make_float2(acc[i][j][2], acc[i][j][3]);
        }
    }
}

// ===========================================================================
// Scan: h_t = c_t*h_{t-1} + v_t; c = sigmoid(-gate), v = sigmoid(gate)*g(hidden)
// ===========================================================================
__device__ __forceinline__ void compute_cv(float hidden, float gate,
                                           float& c, float& v)
{
    const float eg = __expf(gate);
    c = 1.f / (1.f + eg);
    const float z = 1.f - c;
    float gg;
    if (hidden >= 0.f) gg = hidden + 0.5f;
    else               gg = 1.f / (1.f + __expf(-hidden));
    v = z * gg;
}

__global__ __launch_bounds__(256)
void scan_passA()
{
    const int d = threadIdx.x * 4;
    const int k = blockIdx.x;
    const int b = blockIdx.y;
    const size_t base = ((size_t)b * SS + (size_t)k * CLEN) * NN;
    const float4* ph = (const float4*)(g_hg + base + d);
    const float4* pg = (const float4*)(g_hg + base + DD + d);

    float C[4] = {1.f, 1.f, 1.f, 1.f};
    float V[4] = {0.f, 0.f, 0.f, 0.f};
#pragma unroll 4
    for (int s = 0; s < CLEN; s++) {
        const float4 hid = ph[s * (NN / 4)];
        const float4 gat = pg[s * (NN / 4)];
        const float h4[4] = {hid.x, hid.y, hid.z, hid.w};
        const float g4[4] = {gat.x, gat.y, gat.z, gat.w};
#pragma unroll
        for (int j = 0; j < 4; j++) {
            float c, v;
            compute_cv(h4[j], g4[j], c, v);
            V[j] = fmaf(c, V[j], v);
            C[j] *= c;
        }
    }
    const int ch = b * DD + d;
    *(float4*)&g_chunkC[k * (BB * DD) + ch] = make_float4(C[0], C[1], C[2], C[3]);
    *(float4*)&g_chunkV[k * (BB * DD) + ch] = make_float4(V[0], V[1], V[2], V[3]);
}

__global__ __launch_bounds__(128)
void scan_passB()
{
    const int ch = blockIdx.x * 128 + threadIdx.x;   // 0..4095
    float h = 0.f;
#pragma unroll 8
    for (int k = 0; k < NCHUNK; k++) {
        g_h0[k * (BB * DD) + ch] = h;
        h = fmaf(g_chunkC[k * (BB * DD) + ch], h, g_chunkV[k * (BB * DD) + ch]);
    }
}

__global__ __launch_bounds__(256)
void scan_passC(float* __restrict__ out)
{
    const int d = threadIdx.x * 4;
    const int k = blockIdx.x;
    const int b = blockIdx.y;
    const size_t base = ((size_t)b * SS + (size_t)k * CLEN) * NN;
    const float4* ph = (const float4*)(g_hg + base + d);
    const float4* pg = (const float4*)(g_hg + base + DD + d);

    const int ch = b * DD + d;
    const float4 h0v = *(const float4*)&g_h0[k * (BB * DD) + ch];
    float h[4] = {h0v.x, h0v.y, h0v.z, h0v.w};

    float4* po = (float4*)(out + ((size_t)b * SS + (size_t)k * CLEN) * DD + d);
#pragma unroll 4
    for (int s = 0; s < CLEN; s++) {
        const float4 hid = ph[s * (NN / 4)];
        const float4 gat = pg[s * (NN / 4)];
        const float h4[4] = {hid.x, hid.y, hid.z, hid.w};
        const float g4[4] = {gat.x, gat.y, gat.z, gat.w};
#pragma unroll
        for (int j = 0; j < 4; j++) {
            float c, v;
            compute_cv(h4[j], g4[j], c, v);
            h[j] = fmaf(c, h[j], v);
        }
        po[s * (DD / 4)] = make_float4(h[0], h[1], h[2], h[3]);
    }
}

// ===========================================================================
extern "C" void kernel_launch(void* const* d_in, const int* in_sizes, int n_in,
                              void* d_out, int out_size)
{
    const float* x = (const float*)d_in[0];   // [B, S, D]
    const float* W = (const float*)d_in[1];   // [2D, D]
    float* out = (float*)d_out;

    cudaFuncSetAttribute(mingru_gemm,
                         cudaFuncAttributeMaxDynamicSharedMemorySize, GEMM_SMEM);

    dim3 ggrid(NN / TN, MM / TM);            // (16, 128) — x fastest keeps A strip + W in L2
    mingru_gemm<<<ggrid, 256, GEMM_SMEM>>>(x, W);

    dim3 sgrid(NCHUNK, BB);                  // (128, 4)
    scan_passA<<<sgrid, 256>>>();
    scan_passB<<<(BB * DD) / 128, 128>>>();
    scan_passC<<<sgrid, 256>>>(out);
}

// round 7
// speedup vs baseline: 2.5743x; 1.4664x over previous
#include <cuda_runtime.h>
#include <cuda_bf16.h>
#include <cstdint>

// Problem constants
#define BB    4
#define SS    4096
#define DD    1024
#define MM    (BB * SS)      // 16384
#define NN    (2 * DD)       // 2048
#define KK    DD             // 1024

#define NCHUNK 256
#define CLEN   (SS / NCHUNK) // 16

// Scratch (static device globals)
__device__ float g_hg[(size_t)MM * NN];          // 128 MiB
__device__ float g_chunkC[NCHUNK * BB * DD];
__device__ float g_chunkV[NCHUNK * BB * DD];
__device__ float g_h0[NCHUNK * BB * DD];
__device__ __align__(16) __nv_bfloat16 g_Ahi[(size_t)MM * KK];  // 32 MiB
__device__ __align__(16) __nv_bfloat16 g_Alo[(size_t)MM * KK];
__device__ __align__(16) __nv_bfloat16 g_Bhi[(size_t)NN * KK];  // 4 MiB
__device__ __align__(16) __nv_bfloat16 g_Blo[(size_t)NN * KK];

// ===========================================================================
// bf16 split helpers
// ===========================================================================
__device__ __forceinline__ uint32_t f2bf_bits(float x) {
    uint32_t u = __float_as_uint(x);
    return (u + 0x7FFFu + ((u >> 16) & 1u)) >> 16;
}
__device__ __forceinline__ float bf2f(uint32_t b) {
    return __uint_as_float(b << 16);
}
__device__ __forceinline__ void split4(float4 v, uint2& hi, uint2& lo) {
    uint32_t h0 = f2bf_bits(v.x), h1 = f2bf_bits(v.y);
    uint32_t h2 = f2bf_bits(v.z), h3 = f2bf_bits(v.w);
    float l0 = v.x - bf2f(h0), l1 = v.y - bf2f(h1);
    float l2 = v.z - bf2f(h2), l3 = v.w - bf2f(h3);
    uint32_t a0 = f2bf_bits(l0), a1 = f2bf_bits(l1);
    uint32_t a2 = f2bf_bits(l2), a3 = f2bf_bits(l3);
    hi = make_uint2(h0 | (h1 << 16), h2 | (h3 << 16));
    lo = make_uint2(a0 | (a1 << 16), a2 | (a3 << 16));
}

// ===========================================================================
// Convert: x -> (Ahi, Alo), W -> (Bhi, Blo), bf16 row-major [.,K]
// ===========================================================================
#define A4 ((size_t)MM * KK / 4)   // 4194304
#define B4 ((size_t)NN * KK / 4)   // 524288
#define CV_THREADS ((A4 + B4))     // 4718592 total float4s

__global__ __launch_bounds__(256)
void convert_kernel(const float* __restrict__ x, const float* __restrict__ W)
{
    const size_t i = (size_t)blockIdx.x * 256 + threadIdx.x;
    if (i < A4) {
        float4 v = ((const float4*)x)[i];
        uint2 hi, lo;
        split4(v, hi, lo);
        ((uint2*)g_Ahi)[i] = hi;
        ((uint2*)g_Alo)[i] = lo;
    } else {
        const size_t j = i - A4;
        float4 v = ((const float4*)W)[j];
        uint2 hi, lo;
        split4(v, hi, lo);
        ((uint2*)g_Bhi)[j] = hi;
        ((uint2*)g_Blo)[j] = lo;
    }
}

// ===========================================================================
// GEMM: hg = [Ahi|Ahi|Alo] * [Bhi|Blo|Bhi]^T over virtual K = 3072 bf16.
// CTA 128x128, BK=64 bf16, 3-stage cp.async pipeline, ldmatrix frags,
// 256 threads (8 warps, warp tile 64x32), mma.m16n8k16 bf16 -> fp32.
// ===========================================================================
#define TM 128
#define TN 128
#define BKB 64
#define KCHUNKS 48                 // 3 segments x 16 chunks
#define AST 16384                  // A tile bytes per stage (128 x 64 bf16)
#define STAGE_B 32768              // A + B per stage
#define GEMM_SMEM (3 * STAGE_B)    // 98304

#define CP_ASYNC16(dst, src) \
    asm volatile("cp.async.cg.shared.global [%0], [%1], 16;" \
                 :: "r"(dst), "l"(src))
#define CP_COMMIT() asm volatile("cp.async.commit_group;")
#define CP_WAIT1()  asm volatile("cp.async.wait_group 1;")
#define CP_WAIT0()  asm volatile("cp.async.wait_group 0;")
#define LDSM4(r0, r1, r2, r3, addr) \
    asm volatile("ldmatrix.sync.aligned.m8n8.x4.shared.b16 {%0,%1,%2,%3}, [%4];" \
                 : "=r"(r0), "=r"(r1), "=r"(r2), "=r"(r3) : "r"(addr))

__device__ __forceinline__ uint32_t smem_u32(const void* p) {
    uint32_t a;
    asm("{ .reg .u64 t; cvta.to.shared.u64 t, %1; cvt.u32.u64 %0, t; }"
        : "=r"(a) : "l"(p));
    return a;
}

__device__ __forceinline__ void mma_bf16(float& d0, float& d1, float& d2, float& d3,
                                         uint32_t a0, uint32_t a1, uint32_t a2, uint32_t a3,
                                         uint32_t b0, uint32_t b1)
{
    asm volatile(
        "mma.sync.aligned.m16n8k16.row.col.f32.bf16.bf16.f32 "
        "{%0,%1,%2,%3}, {%4,%5,%6,%7}, {%8,%9}, {%0,%1,%2,%3};"
        : "+f"(d0), "+f"(d1), "+f"(d2), "+f"(d3)
        : "r"(a0), "r"(a1), "r"(a2), "r"(a3), "r"(b0), "r"(b1));
}

struct ChunkSrc {
    const __nv_bfloat16* a;
    const __nv_bfloat16* b;
    int kk;
};
__device__ __forceinline__ ChunkSrc chunk_src(int kc) {
    ChunkSrc s;
    const int seg = kc >> 4;
    s.kk = (kc & 15) * BKB;
    s.a = (seg < 2) ? g_Ahi : g_Alo;
    s.b = (seg == 1) ? g_Blo : g_Bhi;
    return s;
}

__global__ __launch_bounds__(256, 1)
void mingru_gemm()
{
    extern __shared__ char smem[];
    const uint32_t sb = smem_u32(smem);
    const int tid = threadIdx.x;
    const int wid = tid >> 5, lid = tid & 31;
    const int m0 = blockIdx.y * TM, n0 = blockIdx.x * TN;

    // cp.async per-thread mapping: 4 x 16B per tile per stage.
    const int crow0 = tid >> 3;          // 0..31 (+32 per iter)
    const int cuc   = tid & 7;           // 16B unit in 128B row
    const uint32_t cdst0 = (uint32_t)(crow0 * 128 + ((cuc * 16) ^ ((crow0 & 7) << 4)));

    // Fragment lane constants
    const int rr = lid & 7, q = lid >> 3;
    const int arow = (q & 1) * 8 + rr;
    const uint32_t acb = (uint32_t)((q >> 1) * 16);
    const int brow = (q >> 1) * 8 + rr;
    const uint32_t bcb = (uint32_t)((q & 1) * 16);
    const uint32_t lxr = (uint32_t)(rr << 4);

    // Warp tiling: 2(m) x 4(n), warp tile 64x32.
    const int wm = (wid >> 2) * 64;
    const int wn = (wid & 3) * 32;
    const int gg = lid >> 2;             // 0..7
    const int t4 = lid & 3;              // 0..3

    float acc[4][4][4];
#pragma unroll
    for (int i = 0; i < 4; i++)
#pragma unroll
        for (int j = 0; j < 4; j++)
#pragma unroll
            for (int e = 0; e < 4; e++) acc[i][j][e] = 0.f;

    // ---- issue chunk kc into stage s ----
    auto issue = [&](int kc, int s) {
        const ChunkSrc cs = chunk_src(kc);
        const uint32_t As = sb + s * STAGE_B;
        const uint32_t Bs = As + AST;
#pragma unroll
        for (int i = 0; i < 4; i++) {
            const int row = crow0 + i * 32;
            const uint32_t d = cdst0 + i * 4096;
            CP_ASYNC16(As + d, cs.a + (size_t)(m0 + row) * KK + cs.kk + cuc * 8);
            CP_ASYNC16(Bs + d, cs.b + (size_t)(n0 + row) * KK + cs.kk + cuc * 8);
        }
        CP_COMMIT();
    };

    issue(0, 0);
    issue(1, 1);

    for (int kc = 0; kc < KCHUNKS; kc++) {
        if (kc == KCHUNKS - 1) { CP_WAIT0(); } else { CP_WAIT1(); }
        __syncthreads();

        const uint32_t As = sb + (kc % 3) * STAGE_B;
        const uint32_t Bs = As + AST;

#pragma unroll
        for (int kt = 0; kt < 4; kt++) {
            uint32_t af[4][4];
#pragma unroll
            for (int i = 0; i < 4; i++) {
                const uint32_t addr = As + (uint32_t)((wm + i * 16 + arow) * 128)
                                    + (((uint32_t)(kt * 32) + acb) ^ lxr);
                LDSM4(af[i][0], af[i][1], af[i][2], af[i][3], addr);
            }
            uint32_t bf[4][2];
            {
                const uint32_t addr0 = Bs + (uint32_t)((wn + brow) * 128)
                                     + (((uint32_t)(kt * 32) + bcb) ^ lxr);
                LDSM4(bf[0][0], bf[0][1], bf[1][0], bf[1][1], addr0);
                LDSM4(bf[2][0], bf[2][1], bf[3][0], bf[3][1], addr0 + 16 * 128);
            }
#pragma unroll
            for (int i = 0; i < 4; i++)
#pragma unroll
                for (int j = 0; j < 4; j++)
                    mma_bf16(acc[i][j][0], acc[i][j][1], acc[i][j][2], acc[i][j][3],
                             af[i][0], af[i][1], af[i][2], af[i][3],
                             bf[j][0], bf[j][1]);
        }

        if (kc + 2 < KCHUNKS) issue(kc + 2, (kc + 2) % 3);
    }

    // Epilogue
#pragma unroll
    for (int i = 0; i < 4; i++) {
        const int r0 = m0 + wm + i * 16 + gg;
#pragma unroll
        for (int j = 0; j < 4; j++) {
            const int c = n0 + wn + j * 8 + t4 * 2;
            *(float2*)(g_hg + (size_t)r0 * NN + c) =
                make_float2(acc[i][j][0], acc[i][j][1]);
            *(float2*)(g_hg + (size_t)(r0 + 8) * NN + c) =
                make_float2(acc[i][j][2], acc[i][j][3]);
        }
    }
}

// ===========================================================================
// Scan: h_t = c_t*h_{t-1} + v_t; c = sigmoid(-gate), v = sigmoid(gate)*g(hidden)
// ===========================================================================
__device__ __forceinline__ void compute_cv(float hidden, float gate,
                                           float& c, float& v)
{
    const float eg = __expf(gate);
    c = 1.f / (1.f + eg);
    const float z = 1.f - c;
    float gg;
    if (hidden >= 0.f) gg = hidden + 0.5f;
    else               gg = 1.f / (1.f + __expf(-hidden));
    v = z * gg;
}

__global__ __launch_bounds__(256)
void scan_passA()
{
    const int d = threadIdx.x * 4;
    const int k = blockIdx.x;
    const int b = blockIdx.y;
    const size_t base = ((size_t)b * SS + (size_t)k * CLEN) * NN;
    const float4* ph = (const float4*)(g_hg + base + d);
    const float4* pg = (const float4*)(g_hg + base + DD + d);

    float C[4] = {1.f, 1.f, 1.f, 1.f};
    float V[4] = {0.f, 0.f, 0.f, 0.f};
#pragma unroll 4
    for (int s = 0; s < CLEN; s++) {
        const float4 hid = ph[s * (NN / 4)];
        const float4 gat = pg[s * (NN / 4)];
        const float h4[4] = {hid.x, hid.y, hid.z, hid.w};
        const float g4[4] = {gat.x, gat.y, gat.z, gat.w};
#pragma unroll
        for (int j = 0; j < 4; j++) {
            float c, v;
            compute_cv(h4[j], g4[j], c, v);
            V[j] = fmaf(c, V[j], v);
            C[j] *= c;
        }
    }
    const int ch = b * DD + d;
    *(float4*)&g_chunkC[k * (BB * DD) + ch] = make_float4(C[0], C[1], C[2], C[3]);
    *(float4*)&g_chunkV[k * (BB * DD) + ch] = make_float4(V[0], V[1], V[2], V[3]);
}

__global__ __launch_bounds__(128)
void scan_passB()
{
    const int ch = blockIdx.x * 128 + threadIdx.x;   // 0..4095
    float h = 0.f;
#pragma unroll 8
    for (int k = 0; k < NCHUNK; k++) {
        g_h0[k * (BB * DD) + ch] = h;
        h = fmaf(g_chunkC[k * (BB * DD) + ch], h, g_chunkV[k * (BB * DD) + ch]);
    }
}

__global__ __launch_bounds__(256)
void scan_passC(float* __restrict__ out)
{
    const int d = threadIdx.x * 4;
    const int k = blockIdx.x;
    const int b = blockIdx.y;
    const size_t base = ((size_t)b * SS + (size_t)k * CLEN) * NN;
    const float4* ph = (const float4*)(g_hg + base + d);
    const float4* pg = (const float4*)(g_hg + base + DD + d);

    const int ch = b * DD + d;
    const float4 h0v = *(const float4*)&g_h0[k * (BB * DD) + ch];
    float h[4] = {h0v.x, h0v.y, h0v.z, h0v.w};

    float4* po = (float4*)(out + ((size_t)b * SS + (size_t)k * CLEN) * DD + d);
#pragma unroll 4
    for (int s = 0; s < CLEN; s++) {
        const float4 hid = ph[s * (NN / 4)];
        const float4 gat = pg[s * (NN / 4)];
        const float h4[4] = {hid.x, hid.y, hid.z, hid.w};
        const float g4[4] = {gat.x, gat.y, gat.z, gat.w};
#pragma unroll
        for (int j = 0; j < 4; j++) {
            float c, v;
            compute_cv(h4[j], g4[j], c, v);
            h[j] = fmaf(c, h[j], v);
        }
        po[s * (DD / 4)] = make_float4(h[0], h[1], h[2], h[3]);
    }
}

// ===========================================================================
extern "C" void kernel_launch(void* const* d_in, const int* in_sizes, int n_in,
                              void* d_out, int out_size)
{
    const float* x = (const float*)d_in[0];   // [B, S, D]
    const float* W = (const float*)d_in[1];   // [2D, D]
    float* out = (float*)d_out;

    cudaFuncSetAttribute(mingru_gemm,
                         cudaFuncAttributeMaxDynamicSharedMemorySize, GEMM_SMEM);

    convert_kernel<<<(unsigned)((A4 + B4) / 256), 256>>>(x, W);

    dim3 ggrid(NN / TN, MM / TM);            // (16, 128) — x fastest: A strip + B' stay in L2
    mingru_gemm<<<ggrid, 256, GEMM_SMEM>>>();

    dim3 sgrid(NCHUNK, BB);                  // (256, 4)
    scan_passA<<<sgrid, 256>>>();
    scan_passB<<<(BB * DD) / 128, 128>>>();
    scan_passC<<<sgrid, 256>>>(out);
}

// round 9
// speedup vs baseline: 2.7474x; 1.0672x over previous
#include <cuda_runtime.h>
#include <cuda_bf16.h>
#include <cstdint>

// Problem constants
#define BB    4
#define SS    4096
#define DD    1024
#define MM    (BB * SS)      // 16384
#define NN    (2 * DD)       // 2048
#define KK    DD             // 1024

#define NCHUNK 256
#define CLEN   (SS / NCHUNK) // 16
#define NCH    (BB * DD)     // 4096 channels

// Scratch (static device globals)
__device__ float g_hg[(size_t)MM * NN];          // 128 MiB
__device__ float g_chunkC[NCHUNK * NCH];
__device__ float g_chunkV[NCHUNK * NCH];
__device__ float g_h0[NCHUNK * NCH];
__device__ __align__(16) __nv_bfloat16 g_Ahi[(size_t)MM * KK];  // 32 MiB
__device__ __align__(16) __nv_bfloat16 g_Alo[(size_t)MM * KK];
__device__ __align__(16) __nv_bfloat16 g_Bhi[(size_t)NN * KK];  // 4 MiB
__device__ __align__(16) __nv_bfloat16 g_Blo[(size_t)NN * KK];

// ===========================================================================
// bf16 split helpers
// ===========================================================================
__device__ __forceinline__ uint32_t f2bf_bits(float x) {
    uint32_t u = __float_as_uint(x);
    return (u + 0x7FFFu + ((u >> 16) & 1u)) >> 16;
}
__device__ __forceinline__ float bf2f(uint32_t b) {
    return __uint_as_float(b << 16);
}
__device__ __forceinline__ void split4(float4 v, uint2& hi, uint2& lo) {
    uint32_t h0 = f2bf_bits(v.x), h1 = f2bf_bits(v.y);
    uint32_t h2 = f2bf_bits(v.z), h3 = f2bf_bits(v.w);
    float l0 = v.x - bf2f(h0), l1 = v.y - bf2f(h1);
    float l2 = v.z - bf2f(h2), l3 = v.w - bf2f(h3);
    uint32_t a0 = f2bf_bits(l0), a1 = f2bf_bits(l1);
    uint32_t a2 = f2bf_bits(l2), a3 = f2bf_bits(l3);
    hi = make_uint2(h0 | (h1 << 16), h2 | (h3 << 16));
    lo = make_uint2(a0 | (a1 << 16), a2 | (a3 << 16));
}

// ===========================================================================
// Convert: x -> (Ahi, Alo), W -> (Bhi, Blo), bf16 row-major [.,K]
// ===========================================================================
#define A4 ((size_t)MM * KK / 4)   // 4194304
#define B4 ((size_t)NN * KK / 4)   // 524288

__global__ __launch_bounds__(256)
void convert_kernel(const float* __restrict__ x, const float* __restrict__ W)
{
    const size_t i = (size_t)blockIdx.x * 256 + threadIdx.x;
    if (i < A4) {
        float4 v = ((const float4*)x)[i];
        uint2 hi, lo;
        split4(v, hi, lo);
        ((uint2*)g_Ahi)[i] = hi;
        ((uint2*)g_Alo)[i] = lo;
    } else {
        const size_t j = i - A4;
        float4 v = ((const float4*)W)[j];
        uint2 hi, lo;
        split4(v, hi, lo);
        ((uint2*)g_Bhi)[j] = hi;
        ((uint2*)g_Blo)[j] = lo;
    }
}

// ===========================================================================
// GEMM: hg = [Ahi|Ahi|Alo] * [Bhi|Blo|Bhi]^T over virtual K = 3072 bf16.
// CTA 128x128, BK=64 bf16, 3-stage cp.async pipeline, ldmatrix frags,
// 256 threads (8 warps, warp tile 64x32), mma.m16n8k16 bf16 -> fp32.
// ===========================================================================
#define TM 128
#define TN 128
#define BKB 64
#define KCHUNKS 48                 // 3 segments x 16 chunks
#define AST 16384                  // A tile bytes per stage (128 x 64 bf16)
#define STAGE_B 32768              // A + B per stage
#define GEMM_SMEM (3 * STAGE_B)    // 98304

#define CP_ASYNC16(dst, src) \
    asm volatile("cp.async.cg.shared.global [%0], [%1], 16;" \
                 :: "r"(dst), "l"(src))
#define CP_COMMIT() asm volatile("cp.async.commit_group;")
#define CP_WAIT1()  asm volatile("cp.async.wait_group 1;")
#define CP_WAIT0()  asm volatile("cp.async.wait_group 0;")
#define LDSM4(r0, r1, r2, r3, addr) \
    asm volatile("ldmatrix.sync.aligned.m8n8.x4.shared.b16 {%0,%1,%2,%3}, [%4];" \
                 : "=r"(r0), "=r"(r1), "=r"(r2), "=r"(r3) : "r"(addr))

__device__ __forceinline__ uint32_t smem_u32(const void* p) {
    uint32_t a;
    asm("{ .reg .u64 t; cvta.to.shared.u64 t, %1; cvt.u32.u64 %0, t; }"
        : "=r"(a) : "l"(p));
    return a;
}

__device__ __forceinline__ void mma_bf16(float& d0, float& d1, float& d2, float& d3,
                                         uint32_t a0, uint32_t a1, uint32_t a2, uint32_t a3,
                                         uint32_t b0, uint32_t b1)
{
    asm volatile(
        "mma.sync.aligned.m16n8k16.row.col.f32.bf16.bf16.f32 "
        "{%0,%1,%2,%3}, {%4,%5,%6,%7}, {%8,%9}, {%0,%1,%2,%3};"
        : "+f"(d0), "+f"(d1), "+f"(d2), "+f"(d3)
        : "r"(a0), "r"(a1), "r"(a2), "r"(a3), "r"(b0), "r"(b1));
}

struct ChunkSrc {
    const __nv_bfloat16* a;
    const __nv_bfloat16* b;
    int kk;
};
__device__ __forceinline__ ChunkSrc chunk_src(int kc) {
    ChunkSrc s;
    const int seg = kc >> 4;
    s.kk = (kc & 15) * BKB;
    s.a = (seg < 2) ? g_Ahi : g_Alo;
    s.b = (seg == 1) ? g_Blo : g_Bhi;
    return s;
}

__global__ __launch_bounds__(256, 1)
void mingru_gemm()
{
    extern __shared__ char smem[];
    const uint32_t sb = smem_u32(smem);
    const int tid = threadIdx.x;
    const int wid = tid >> 5, lid = tid & 31;
    const int m0 = blockIdx.y * TM, n0 = blockIdx.x * TN;

    // cp.async per-thread mapping: 4 x 16B per tile per stage.
    const int crow0 = tid >> 3;          // 0..31 (+32 per iter)
    const int cuc   = tid & 7;           // 16B unit in 128B row
    const uint32_t cdst0 = (uint32_t)(crow0 * 128 + ((cuc * 16) ^ ((crow0 & 7) << 4)));

    // Fragment lane constants
    const int rr = lid & 7, q = lid >> 3;
    const int arow = (q & 1) * 8 + rr;
    const uint32_t acb = (uint32_t)((q >> 1) * 16);
    const int brow = (q >> 1) * 8 + rr;
    const uint32_t bcb = (uint32_t)((q & 1) * 16);
    const uint32_t lxr = (uint32_t)(rr << 4);

    // Warp tiling: 2(m) x 4(n), warp tile 64x32.
    const int wm = (wid >> 2) * 64;
    const int wn = (wid & 3) * 32;
    const int gg = lid >> 2;             // 0..7
    const int t4 = lid & 3;              // 0..3

    float acc[4][4][4];
#pragma unroll
    for (int i = 0; i < 4; i++)
#pragma unroll
        for (int j = 0; j < 4; j++)
#pragma unroll
            for (int e = 0; e < 4; e++) acc[i][j][e] = 0.f;

    auto issue = [&](int kc, int s) {
        const ChunkSrc cs = chunk_src(kc);
        const uint32_t As = sb + s * STAGE_B;
        const uint32_t Bs = As + AST;
#pragma unroll
        for (int i = 0; i < 4; i++) {
            const int row = crow0 + i * 32;
            const uint32_t d = cdst0 + i * 4096;
            CP_ASYNC16(As + d, cs.a + (size_t)(m0 + row) * KK + cs.kk + cuc * 8);
            CP_ASYNC16(Bs + d, cs.b + (size_t)(n0 + row) * KK + cs.kk + cuc * 8);
        }
        CP_COMMIT();
    };

    issue(0, 0);
    issue(1, 1);

    for (int kc = 0; kc < KCHUNKS; kc++) {
        if (kc == KCHUNKS - 1) { CP_WAIT0(); } else { CP_WAIT1(); }
        __syncthreads();

        const uint32_t As = sb + (kc % 3) * STAGE_B;
        const uint32_t Bs = As + AST;

#pragma unroll
        for (int kt = 0; kt < 4; kt++) {
            uint32_t af[4][4];
#pragma unroll
            for (int i = 0; i < 4; i++) {
                const uint32_t addr = As + (uint32_t)((wm + i * 16 + arow) * 128)
                                    + (((uint32_t)(kt * 32) + acb) ^ lxr);
                LDSM4(af[i][0], af[i][1], af[i][2], af[i][3], addr);
            }
            uint32_t bf[4][2];
            {
                const uint32_t addr0 = Bs + (uint32_t)((wn + brow) * 128)
                                     + (((uint32_t)(kt * 32) + bcb) ^ lxr);
                LDSM4(bf[0][0], bf[0][1], bf[1][0], bf[1][1], addr0);
                LDSM4(bf[2][0], bf[2][1], bf[3][0], bf[3][1], addr0 + 16 * 128);
            }
#pragma unroll
            for (int i = 0; i < 4; i++)
#pragma unroll
                for (int j = 0; j < 4; j++)
                    mma_bf16(acc[i][j][0], acc[i][j][1], acc[i][j][2], acc[i][j][3],
                             af[i][0], af[i][1], af[i][2], af[i][3],
                             bf[j][0], bf[j][1]);
        }

        if (kc + 2 < KCHUNKS) issue(kc + 2, (kc + 2) % 3);
    }

    // Epilogue
#pragma unroll
    for (int i = 0; i < 4; i++) {
        const int r0 = m0 + wm + i * 16 + gg;
#pragma unroll
        for (int j = 0; j < 4; j++) {
            const int c = n0 + wn + j * 8 + t4 * 2;
            *(float2*)(g_hg + (size_t)r0 * NN + c) =
                make_float2(acc[i][j][0], acc[i][j][1]);
            *(float2*)(g_hg + (size_t)(r0 + 8) * NN + c) =
                make_float2(acc[i][j][2], acc[i][j][3]);
        }
    }
}

// ===========================================================================
// Scan: h_t = c_t*h_{t-1} + v_t; c = sigmoid(-gate), v = sigmoid(gate)*g(hidden)
// ===========================================================================
__device__ __forceinline__ void compute_cv(float hidden, float gate,
                                           float& c, float& v)
{
    const float eg = __expf(gate);
    c = 1.f / (1.f + eg);
    const float z = 1.f - c;
    float gg;
    if (hidden >= 0.f) gg = hidden + 0.5f;
    else               gg = 1.f / (1.f + __expf(-hidden));
    v = z * gg;
}

__global__ __launch_bounds__(256)
void scan_passA()
{
    const int d = threadIdx.x * 4;
    const int k = blockIdx.x;
    const int b = blockIdx.y;
    const size_t base = ((size_t)b * SS + (size_t)k * CLEN) * NN;
    const float4* ph = (const float4*)(g_hg + base + d);
    const float4* pg = (const float4*)(g_hg + base + DD + d);

    float C[4] = {1.f, 1.f, 1.f, 1.f};
    float V[4] = {0.f, 0.f, 0.f, 0.f};
#pragma unroll 4
    for (int s = 0; s < CLEN; s++) {
        const float4 hid = ph[s * (NN / 4)];
        const float4 gat = pg[s * (NN / 4)];
        const float h4[4] = {hid.x, hid.y, hid.z, hid.w};
        const float g4[4] = {gat.x, gat.y, gat.z, gat.w};
#pragma unroll
        for (int j = 0; j < 4; j++) {
            float c, v;
            compute_cv(h4[j], g4[j], c, v);
            V[j] = fmaf(c, V[j], v);
            C[j] *= c;
        }
    }
    const int ch = b * DD + d;
    *(float4*)&g_chunkC[k * NCH + ch] = make_float4(C[0], C[1], C[2], C[3]);
    *(float4*)&g_chunkV[k * NCH + ch] = make_float4(V[0], V[1], V[2], V[3]);
}

// Warp-per-channel associative scan over the 256 chunk transforms.
// Lane l owns chunks [8l, 8l+8). Compose op (applied prev-then-cur):
//   C = Cp*Cc, V = Cc*Vp + Vc.
#define KPL (NCHUNK / 32)   // 8 chunks per lane
__global__ __launch_bounds__(256)
void scan_passB()
{
    const int warp = (blockIdx.x * 256 + threadIdx.x) >> 5;  // 0..4095 == ch
    const int lane = threadIdx.x & 31;
    const int ch = warp;

    float c8[KPL], v8[KPL];
#pragma unroll
    for (int j = 0; j < KPL; j++) {
        const int k = lane * KPL + j;
        c8[j] = g_chunkC[k * NCH + ch];
        v8[j] = g_chunkV[k * NCH + ch];
    }
    // Compose this lane's 8 transforms (prev-to-cur order).
    float C = c8[0], V = v8[0];
#pragma unroll
    for (int j = 1; j < KPL; j++) {
        V = fmaf(c8[j], V, v8[j]);
        C *= c8[j];
    }
    // Inclusive Kogge-Stone scan across lanes.
#pragma unroll
    for (int off = 1; off < 32; off <<= 1) {
        const float Cp = __shfl_up_sync(0xFFFFFFFFu, C, off);
        const float Vp = __shfl_up_sync(0xFFFFFFFFu, V, off);
        if (lane >= off) {
            V = fmaf(C, Vp, V);
            C *= Cp;
        }
    }
    // h entering this lane's group = inclusive V of lane-1 applied to h0=0.
    const float Vprev = __shfl_up_sync(0xFFFFFFFFu, V, 1);
    float h = (lane == 0) ? 0.f : Vprev;
#pragma unroll
    for (int j = 0; j < KPL; j++) {
        const int k = lane * KPL + j;
        g_h0[k * NCH + ch] = h;
        h = fmaf(c8[j], h, v8[j]);
    }
}

__global__ __launch_bounds__(256)
void scan_passC(float* __restrict__ out)
{
    const int d = threadIdx.x * 4;
    const int k = blockIdx.x;
    const int b = blockIdx.y;
    const size_t base = ((size_t)b * SS + (size_t)k * CLEN) * NN;
    const float4* ph = (const float4*)(g_hg + base + d);
    const float4* pg = (const float4*)(g_hg + base + DD + d);

    const int ch = b * DD + d;
    const float4 h0v = *(const float4*)&g_h0[k * NCH + ch];
    float h[4] = {h0v.x, h0v.y, h0v.z, h0v.w};

    float4* po = (float4*)(out + ((size_t)b * SS + (size_t)k * CLEN) * DD + d);
#pragma unroll 4
    for (int s = 0; s < CLEN; s++) {
        const float4 hid = ph[s * (NN / 4)];
        const float4 gat = pg[s * (NN / 4)];
        const float h4[4] = {hid.x, hid.y, hid.z, hid.w};
        const float g4[4] = {gat.x, gat.y, gat.z, gat.w};
#pragma unroll
        for (int j = 0; j < 4; j++) {
            float c, v;
            compute_cv(h4[j], g4[j], c, v);
            h[j] = fmaf(c, h[j], v);
        }
        po[s * (DD / 4)] = make_float4(h[0], h[1], h[2], h[3]);
    }
}

// ===========================================================================
extern "C" void kernel_launch(void* const* d_in, const int* in_sizes, int n_in,
                              void* d_out, int out_size)
{
    const float* x = (const float*)d_in[0];   // [B, S, D]
    const float* W = (const float*)d_in[1];   // [2D, D]
    float* out = (float*)d_out;

    cudaFuncSetAttribute(mingru_gemm,
                         cudaFuncAttributeMaxDynamicSharedMemorySize, GEMM_SMEM);

    convert_kernel<<<(unsigned)((A4 + B4) / 256), 256>>>(x, W);

    dim3 ggrid(NN / TN, MM / TM);            // (16, 128)
    mingru_gemm<<<ggrid, 256, GEMM_SMEM>>>();

    dim3 sgrid(NCHUNK, BB);                  // (256, 4)
    scan_passA<<<sgrid, 256>>>();
    scan_passB<<<(NCH * 32) / 256, 256>>>(); // 512 CTAs, warp per channel
    scan_passC<<<sgrid, 256>>>(out);
}

// round 10
// speedup vs baseline: 3.1318x; 1.1399x over previous
#include <cuda_runtime.h>
#include <cuda_bf16.h>
#include <cstdint>

// Problem constants
#define BB    4
#define SS    4096
#define DD    1024
#define MM    (BB * SS)      // 16384
#define NN    (2 * DD)       // 2048
#define KK    DD             // 1024

#define NCHUNK 256
#define CLEN   (SS / NCHUNK) // 16
#define NCH    (BB * DD)     // 4096 channels

// Scratch (static device globals)
__device__ float g_hg[(size_t)MM * NN];          // 128 MiB
__device__ float g_chunkC[NCHUNK * NCH];
__device__ float g_chunkV[NCHUNK * NCH];
__device__ float g_h0[NCHUNK * NCH];
__device__ __align__(16) __nv_bfloat16 g_Ahi[(size_t)MM * KK];  // 32 MiB
__device__ __align__(16) __nv_bfloat16 g_Alo[(size_t)MM * KK];
__device__ __align__(16) __nv_bfloat16 g_Bhi[(size_t)NN * KK];  // 4 MiB
__device__ __align__(16) __nv_bfloat16 g_Blo[(size_t)NN * KK];

// ===========================================================================
// bf16 split helpers
// ===========================================================================
__device__ __forceinline__ uint32_t f2bf_bits(float x) {
    uint32_t u = __float_as_uint(x);
    return (u + 0x7FFFu + ((u >> 16) & 1u)) >> 16;
}
__device__ __forceinline__ float bf2f(uint32_t b) {
    return __uint_as_float(b << 16);
}
__device__ __forceinline__ void split4(float4 v, uint2& hi, uint2& lo) {
    uint32_t h0 = f2bf_bits(v.x), h1 = f2bf_bits(v.y);
    uint32_t h2 = f2bf_bits(v.z), h3 = f2bf_bits(v.w);
    float l0 = v.x - bf2f(h0), l1 = v.y - bf2f(h1);
    float l2 = v.z - bf2f(h2), l3 = v.w - bf2f(h3);
    uint32_t a0 = f2bf_bits(l0), a1 = f2bf_bits(l1);
    uint32_t a2 = f2bf_bits(l2), a3 = f2bf_bits(l3);
    hi = make_uint2(h0 | (h1 << 16), h2 | (h3 << 16));
    lo = make_uint2(a0 | (a1 << 16), a2 | (a3 << 16));
}

// ===========================================================================
// Convert: x -> (Ahi, Alo), W -> (Bhi, Blo), bf16 row-major [.,K]
// ===========================================================================
#define A4 ((size_t)MM * KK / 4)   // 4194304
#define B4 ((size_t)NN * KK / 4)   // 524288

__global__ __launch_bounds__(256)
void convert_kernel(const float* __restrict__ x, const float* __restrict__ W)
{
    const size_t i = (size_t)blockIdx.x * 256 + threadIdx.x;
    if (i < A4) {
        float4 v = ((const float4*)x)[i];
        uint2 hi, lo;
        split4(v, hi, lo);
        ((uint2*)g_Ahi)[i] = hi;
        ((uint2*)g_Alo)[i] = lo;
    } else {
        const size_t j = i - A4;
        float4 v = ((const float4*)W)[j];
        uint2 hi, lo;
        split4(v, hi, lo);
        ((uint2*)g_Bhi)[j] = hi;
        ((uint2*)g_Blo)[j] = lo;
    }
}

// ===========================================================================
// GEMM: hg = [Ahi|Ahi|Alo] * [Bhi|Blo|Bhi]^T over virtual K = 3072 bf16.
// CTA 128x128, BK=64 bf16, 3-stage cp.async pipeline, ldmatrix frags,
// 256 threads (8 warps, warp tile 64x32), mma.m16n8k16 bf16 -> fp32.
// 2 CTAs/SM (192KB smem, <=128 regs) to fill sync bubbles.
// ===========================================================================
#define TM 128
#define TN 128
#define BKB 64
#define KCHUNKS 48                 // 3 segments x 16 chunks
#define AST 16384                  // A tile bytes per stage (128 x 64 bf16)
#define STAGE_B 32768              // A + B per stage
#define GEMM_SMEM (3 * STAGE_B)    // 98304

#define CP_ASYNC16(dst, src) \
    asm volatile("cp.async.cg.shared.global [%0], [%1], 16;" \
                 :: "r"(dst), "l"(src))
#define CP_COMMIT() asm volatile("cp.async.commit_group;")
#define CP_WAIT1()  asm volatile("cp.async.wait_group 1;")
#define CP_WAIT0()  asm volatile("cp.async.wait_group 0;")
#define LDSM4(r0, r1, r2, r3, addr) \
    asm volatile("ldmatrix.sync.aligned.m8n8.x4.shared.b16 {%0,%1,%2,%3}, [%4];" \
                 : "=r"(r0), "=r"(r1), "=r"(r2), "=r"(r3) : "r"(addr))

__device__ __forceinline__ uint32_t smem_u32(const void* p) {
    uint32_t a;
    asm("{ .reg .u64 t; cvta.to.shared.u64 t, %1; cvt.u32.u64 %0, t; }"
        : "=r"(a) : "l"(p));
    return a;
}

__device__ __forceinline__ void mma_bf16(float& d0, float& d1, float& d2, float& d3,
                                         uint32_t a0, uint32_t a1, uint32_t a2, uint32_t a3,
                                         uint32_t b0, uint32_t b1)
{
    asm volatile(
        "mma.sync.aligned.m16n8k16.row.col.f32.bf16.bf16.f32 "
        "{%0,%1,%2,%3}, {%4,%5,%6,%7}, {%8,%9}, {%0,%1,%2,%3};"
        : "+f"(d0), "+f"(d1), "+f"(d2), "+f"(d3)
        : "r"(a0), "r"(a1), "r"(a2), "r"(a3), "r"(b0), "r"(b1));
}

struct ChunkSrc {
    const __nv_bfloat16* a;
    const __nv_bfloat16* b;
    int kk;
};
__device__ __forceinline__ ChunkSrc chunk_src(int kc) {
    ChunkSrc s;
    const int seg = kc >> 4;
    s.kk = (kc & 15) * BKB;
    s.a = (seg < 2) ? g_Ahi : g_Alo;
    s.b = (seg == 1) ? g_Blo : g_Bhi;
    return s;
}

__global__ __launch_bounds__(256, 2)
void mingru_gemm()
{
    extern __shared__ char smem[];
    const uint32_t sb = smem_u32(smem);
    const int tid = threadIdx.x;
    const int wid = tid >> 5, lid = tid & 31;
    const int m0 = blockIdx.y * TM, n0 = blockIdx.x * TN;

    // cp.async per-thread mapping: 4 x 16B per tile per stage.
    const int crow0 = tid >> 3;          // 0..31 (+32 per iter)
    const int cuc   = tid & 7;           // 16B unit in 128B row
    const uint32_t cdst0 = (uint32_t)(crow0 * 128 + ((cuc * 16) ^ ((crow0 & 7) << 4)));

    // Fragment lane constants
    const int rr = lid & 7, q = lid >> 3;
    const int arow = (q & 1) * 8 + rr;
    const uint32_t acb = (uint32_t)((q >> 1) * 16);
    const int brow = (q >> 1) * 8 + rr;
    const uint32_t bcb = (uint32_t)((q & 1) * 16);
    const uint32_t lxr = (uint32_t)(rr << 4);

    // Warp tiling: 2(m) x 4(n), warp tile 64x32.
    const int wm = (wid >> 2) * 64;
    const int wn = (wid & 3) * 32;
    const int gg = lid >> 2;             // 0..7
    const int t4 = lid & 3;              // 0..3

    float acc[4][4][4];
#pragma unroll
    for (int i = 0; i < 4; i++)
#pragma unroll
        for (int j = 0; j < 4; j++)
#pragma unroll
            for (int e = 0; e < 4; e++) acc[i][j][e] = 0.f;

    auto issue = [&](int kc, int s) {
        const ChunkSrc cs = chunk_src(kc);
        const uint32_t As = sb + s * STAGE_B;
        const uint32_t Bs = As + AST;
#pragma unroll
        for (int i = 0; i < 4; i++) {
            const int row = crow0 + i * 32;
            const uint32_t d = cdst0 + i * 4096;
            CP_ASYNC16(As + d, cs.a + (size_t)(m0 + row) * KK + cs.kk + cuc * 8);
            CP_ASYNC16(Bs + d, cs.b + (size_t)(n0 + row) * KK + cs.kk + cuc * 8);
        }
        CP_COMMIT();
    };

    issue(0, 0);
    issue(1, 1);

    for (int kc = 0; kc < KCHUNKS; kc++) {
        if (kc == KCHUNKS - 1) { CP_WAIT0(); } else { CP_WAIT1(); }
        __syncthreads();

        // Stage (kc+2)%3 == (kc-1)%3 was fully consumed before the sync above:
        // issue its refill now so the copy overlaps this chunk's MMAs.
        if (kc + 2 < KCHUNKS) issue(kc + 2, (kc + 2) % 3);

        const uint32_t As = sb + (kc % 3) * STAGE_B;
        const uint32_t Bs = As + AST;

#pragma unroll
        for (int kt = 0; kt < 4; kt++) {
            uint32_t af[4][4];
#pragma unroll
            for (int i = 0; i < 4; i++) {
                const uint32_t addr = As + (uint32_t)((wm + i * 16 + arow) * 128)
                                    + (((uint32_t)(kt * 32) + acb) ^ lxr);
                LDSM4(af[i][0], af[i][1], af[i][2], af[i][3], addr);
            }
            uint32_t bf[4][2];
            {
                const uint32_t addr0 = Bs + (uint32_t)((wn + brow) * 128)
                                     + (((uint32_t)(kt * 32) + bcb) ^ lxr);
                LDSM4(bf[0][0], bf[0][1], bf[1][0], bf[1][1], addr0);
                LDSM4(bf[2][0], bf[2][1], bf[3][0], bf[3][1], addr0 + 16 * 128);
            }
#pragma unroll
            for (int i = 0; i < 4; i++)
#pragma unroll
                for (int j = 0; j < 4; j++)
                    mma_bf16(acc[i][j][0], acc[i][j][1], acc[i][j][2], acc[i][j][3],
                             af[i][0], af[i][1], af[i][2], af[i][3],
                             bf[j][0], bf[j][1]);
        }
    }

    // Epilogue
#pragma unroll
    for (int i = 0; i < 4; i++) {
        const int r0 = m0 + wm + i * 16 + gg;
#pragma unroll
        for (int j = 0; j < 4; j++) {
            const int c = n0 + wn + j * 8 + t4 * 2;
            *(float2*)(g_hg + (size_t)r0 * NN + c) =
                make_float2(acc[i][j][0], acc[i][j][1]);
            *(float2*)(g_hg + (size_t)(r0 + 8) * NN + c) =
                make_float2(acc[i][j][2], acc[i][j][3]);
        }
    }
}

// ===========================================================================
// Scan: h_t = c_t*h_{t-1} + v_t; c = sigmoid(-gate), v = sigmoid(gate)*g(hidden)
// ===========================================================================
__device__ __forceinline__ void compute_cv(float hidden, float gate,
                                           float& c, float& v)
{
    const float eg = __expf(gate);
    c = 1.f / (1.f + eg);
    const float z = 1.f - c;
    float gg;
    if (hidden >= 0.f) gg = hidden + 0.5f;
    else               gg = 1.f / (1.f + __expf(-hidden));
    v = z * gg;
}

__global__ __launch_bounds__(256)
void scan_passA()
{
    const int d = threadIdx.x * 4;
    const int k = blockIdx.x;
    const int b = blockIdx.y;
    const size_t base = ((size_t)b * SS + (size_t)k * CLEN) * NN;
    const float4* ph = (const float4*)(g_hg + base + d);
    const float4* pg = (const float4*)(g_hg + base + DD + d);

    float C[4] = {1.f, 1.f, 1.f, 1.f};
    float V[4] = {0.f, 0.f, 0.f, 0.f};
#pragma unroll 4
    for (int s = 0; s < CLEN; s++) {
        const float4 hid = ph[s * (NN / 4)];
        const float4 gat = pg[s * (NN / 4)];
        const float h4[4] = {hid.x, hid.y, hid.z, hid.w};
        const float g4[4] = {gat.x, gat.y, gat.z, gat.w};
#pragma unroll
        for (int j = 0; j < 4; j++) {
            float c, v;
            compute_cv(h4[j], g4[j], c, v);
            V[j] = fmaf(c, V[j], v);
            C[j] *= c;
        }
    }
    const int ch = b * DD + d;
    *(float4*)&g_chunkC[k * NCH + ch] = make_float4(C[0], C[1], C[2], C[3]);
    *(float4*)&g_chunkV[k * NCH + ch] = make_float4(V[0], V[1], V[2], V[3]);
}

// Warp-per-channel associative scan over the 256 chunk transforms.
#define KPL (NCHUNK / 32)   // 8 chunks per lane
__global__ __launch_bounds__(256)
void scan_passB()
{
    const int warp = (blockIdx.x * 256 + threadIdx.x) >> 5;  // 0..4095 == ch
    const int lane = threadIdx.x & 31;
    const int ch = warp;

    float c8[KPL], v8[KPL];
#pragma unroll
    for (int j = 0; j < KPL; j++) {
        const int k = lane * KPL + j;
        c8[j] = g_chunkC[k * NCH + ch];
        v8[j] = g_chunkV[k * NCH + ch];
    }
    float C = c8[0], V = v8[0];
#pragma unroll
    for (int j = 1; j < KPL; j++) {
        V = fmaf(c8[j], V, v8[j]);
        C *= c8[j];
    }
#pragma unroll
    for (int off = 1; off < 32; off <<= 1) {
        const float Cp = __shfl_up_sync(0xFFFFFFFFu, C, off);
        const float Vp = __shfl_up_sync(0xFFFFFFFFu, V, off);
        if (lane >= off) {
            V = fmaf(C, Vp, V);
            C *= Cp;
        }
    }
    const float Vprev = __shfl_up_sync(0xFFFFFFFFu, V, 1);
    float h = (lane == 0) ? 0.f : Vprev;
#pragma unroll
    for (int j = 0; j < KPL; j++) {
        const int k = lane * KPL + j;
        g_h0[k * NCH + ch] = h;
        h = fmaf(c8[j], h, v8[j]);
    }
}

__global__ __launch_bounds__(256)
void scan_passC(float* __restrict__ out)
{
    const int d = threadIdx.x * 4;
    const int k = blockIdx.x;
    const int b = blockIdx.y;
    const size_t base = ((size_t)b * SS + (size_t)k * CLEN) * NN;
    const float4* ph = (const float4*)(g_hg + base + d);
    const float4* pg = (const float4*)(g_hg + base + DD + d);

    const int ch = b * DD + d;
    const float4 h0v = *(const float4*)&g_h0[k * NCH + ch];
    float h[4] = {h0v.x, h0v.y, h0v.z, h0v.w};

    float4* po = (float4*)(out + ((size_t)b * SS + (size_t)k * CLEN) * DD + d);
#pragma unroll 4
    for (int s = 0; s < CLEN; s++) {
        const float4 hid = ph[s * (NN / 4)];
        const float4 gat = pg[s * (NN / 4)];
        const float h4[4] = {hid.x, hid.y, hid.z, hid.w};
        const float g4[4] = {gat.x, gat.y, gat.z, gat.w};
#pragma unroll
        for (int j = 0; j < 4; j++) {
            float c, v;
            compute_cv(h4[j], g4[j], c, v);
            h[j] = fmaf(c, h[j], v);
        }
        po[s * (DD / 4)] = make_float4(h[0], h[1], h[2], h[3]);
    }
}

// ===========================================================================
extern "C" void kernel_launch(void* const* d_in, const int* in_sizes, int n_in,
                              void* d_out, int out_size)
{
    const float* x = (const float*)d_in[0];   // [B, S, D]
    const float* W = (const float*)d_in[1];   // [2D, D]
    float* out = (float*)d_out;

    cudaFuncSetAttribute(mingru_gemm,
                         cudaFuncAttributeMaxDynamicSharedMemorySize, GEMM_SMEM);

    convert_kernel<<<(unsigned)((A4 + B4) / 256), 256>>>(x, W);

    dim3 ggrid(NN / TN, MM / TM);            // (16, 128)
    mingru_gemm<<<ggrid, 256, GEMM_SMEM>>>();

    dim3 sgrid(NCHUNK, BB);                  // (256, 4)
    scan_passA<<<sgrid, 256>>>();
    scan_passB<<<(NCH * 32) / 256, 256>>>(); // 512 CTAs, warp per channel
    scan_passC<<<sgrid, 256>>>(out);
}